// round 1
// baseline (speedup 1.0000x reference)
#include <cuda_runtime.h>
#include <math.h>

// ---------------- problem constants ----------------
#define Bq     512   // batch
#define Hd     512   // hidden
#define G4     2048  // 4*H
#define FEAT   128
#define T_ENC  512
#define PRED   96

#define GRIDSZ 128
#define NTHR   256

// tile: 64 batch-rows x (4 gates x 32 h-cols) = 64 x 128 gate columns
#define BM 64
#define BN 128
#define KB 16

// ---------------- persistent device state ----------------
__device__ float g_h0[2][Bq * Hd];      // layer0 h, double buffered
__device__ float g_h1[2][Bq * Hd];      // layer1 h, double buffered
__device__ float g_fc_part[16][Bq];     // per-col-tile partial fc dots
__device__ float g_dec_in0[Bq];         // decoder seed input
__device__ unsigned int g_bar;          // grid barrier counter (monotonic per launch)

struct SM {
    union {
        struct { float As[KB][BM]; float Ws[KB][BN]; } ld; // 12 KB
        float gates[BM][BN];                               // 32 KB
    };
};

// ---------------- grid barrier ----------------
__device__ __forceinline__ void grid_bar(unsigned int* phase) {
    __syncthreads();
    if (threadIdx.x == 0) {
        __threadfence();
        atomicAdd(&g_bar, 1u);
        ++(*phase);
        const unsigned int target = (*phase) * (unsigned int)GRIDSZ;
        for (;;) {
            unsigned int v;
            asm volatile("ld.global.acquire.gpu.u32 %0, [%1];" : "=r"(v) : "l"(&g_bar));
            if (v >= target) break;
            __nanosleep(64);
        }
        __threadfence();
    }
    __syncthreads();
}

__device__ __forceinline__ float sigmoidf_(float x) {
    return 1.0f / (1.0f + expf(-x));
}

// ---------------- GEMM core: acc[4][8] += A[64 x K] * W^T (gate-remapped rows) -----
// A: row-major, row stride lda. W: row-major [2048 x ldw]; the 128 output cols j of
// this CTA map to W row  wrow(j) = (j/32)*512 + hc0 + (j%32)  (4 gates x 32 cols).
__device__ __forceinline__ void gemm_acc(float acc[4][8], SM& sm,
                                         const float* __restrict__ A, int lda,
                                         const float* __restrict__ W, int ldw,
                                         int K, int bm0, int hc0) {
    const int tid = threadIdx.x;
    const int ty = tid >> 4;         // 0..15
    const int tx = tid & 15;         // 0..15
    const int lr = tid >> 2;         // 0..63
    const int lk = (tid & 3) << 2;   // 0,4,8,12

    const int wr0 = ((lr >> 5) * 512) + hc0 + (lr & 31);
    const int wr1 = (((lr >> 5) + 2) * 512) + hc0 + (lr & 31);

    const float* Arow  = A + (bm0 + lr) * lda + lk;
    const float* Wrow0 = W + wr0 * ldw + lk;
    const float* Wrow1 = W + wr1 * ldw + lk;

    for (int k0 = 0; k0 < K; k0 += KB) {
        float4 av = *(const float4*)(Arow  + k0);
        float4 w0 = *(const float4*)(Wrow0 + k0);
        float4 w1 = *(const float4*)(Wrow1 + k0);
        __syncthreads();   // previous chunk's reads done before overwrite
        sm.ld.As[lk + 0][lr] = av.x;
        sm.ld.As[lk + 1][lr] = av.y;
        sm.ld.As[lk + 2][lr] = av.z;
        sm.ld.As[lk + 3][lr] = av.w;
        sm.ld.Ws[lk + 0][lr] = w0.x;
        sm.ld.Ws[lk + 1][lr] = w0.y;
        sm.ld.Ws[lk + 2][lr] = w0.z;
        sm.ld.Ws[lk + 3][lr] = w0.w;
        sm.ld.Ws[lk + 0][lr + 64] = w1.x;
        sm.ld.Ws[lk + 1][lr + 64] = w1.y;
        sm.ld.Ws[lk + 2][lr + 64] = w1.z;
        sm.ld.Ws[lk + 3][lr + 64] = w1.w;
        __syncthreads();
#pragma unroll
        for (int kk = 0; kk < KB; ++kk) {
            float4 a  = *(const float4*)&sm.ld.As[kk][ty * 4];
            float4 p  = *(const float4*)&sm.ld.Ws[kk][tx * 8];
            float4 q  = *(const float4*)&sm.ld.Ws[kk][tx * 8 + 4];
            float av4[4] = {a.x, a.y, a.z, a.w};
            float wv[8]  = {p.x, p.y, p.z, p.w, q.x, q.y, q.z, q.w};
#pragma unroll
            for (int i = 0; i < 4; ++i)
#pragma unroll
                for (int j = 0; j < 8; ++j)
                    acc[i][j] += av4[i] * wv[j];
        }
    }
}

// ---------------- stage epilogue: bias + (optional rank1) + LSTM pointwise ------
// MODE 0: plain (encoder). MODE 1: decoder layer0 (rank-1 input, dec-in logic,
// writes previous step's output). MODE 2: decoder layer1 (fc partial dot).
template <int MODE>
__device__ __forceinline__ void epilogue(float acc[4][8], SM& sm, float cR[8],
                                         const float* __restrict__ b_ih,
                                         const float* __restrict__ b_hh,
                                         float* __restrict__ h_out,
                                         int bm0, int hc0, int tileN,
                                         const float* __restrict__ rank1w,
                                         const float* __restrict__ y,
                                         const int* __restrict__ tf_mask,
                                         float* __restrict__ d_out, int t,
                                         const float* __restrict__ fcW,
                                         const float* __restrict__ fc_b) {
    const int tid = threadIdx.x;
    const int ty = tid >> 4, tx = tid & 15;
    __syncthreads();   // all GEMM smem reads done before aliasing with gates
#pragma unroll
    for (int i = 0; i < 4; ++i)
#pragma unroll
        for (int j = 0; j < 8; ++j)
            sm.gates[ty * 4 + i][tx * 8 + j] = acc[i][j];
    __syncthreads();

    const int pc  = tid & 31;          // h-column within 32-band
    const int pr0 = (tid >> 5) * 8;    // 8 rows per thread
    const int col = hc0 + pc;

    const float bi = b_ih[col]        + b_hh[col];
    const float bf = b_ih[512 + col]  + b_hh[512 + col];
    const float bg = b_ih[1024 + col] + b_hh[1024 + col];
    const float bo = b_ih[1536 + col] + b_hh[1536 + col];

    float w1i = 0.f, w1f = 0.f, w1g = 0.f, w1o = 0.f, fcw = 0.f;
    if (MODE == 1) {
        w1i = rank1w[col];
        w1f = rank1w[512 + col];
        w1g = rank1w[1024 + col];
        w1o = rank1w[1536 + col];
    }
    if (MODE == 2) fcw = fcW[col];

    const bool tfprev = (MODE == 1 && t > 0) ? (tf_mask[t - 1] != 0) : false;

#pragma unroll
    for (int q = 0; q < 8; ++q) {
        const int r = pr0 + q;
        const int b = bm0 + r;

        float xi = sm.gates[r][pc]        + bi;
        float xf = sm.gates[r][32 + pc]   + bf;
        float xg = sm.gates[r][64 + pc]   + bg;
        float xo = sm.gates[r][96 + pc]   + bo;

        if (MODE == 1) {
            float din;
            if (t == 0) {
                din = g_dec_in0[b];
            } else {
                float out = fc_b[0];
#pragma unroll
                for (int j = 0; j < 16; ++j) out += g_fc_part[j][b];
                if (tileN == 0 && pc == 0) d_out[b * PRED + (t - 1)] = out;
                din = tfprev ? y[b * PRED + t] : out;
            }
            xi += din * w1i;
            xf += din * w1f;
            xg += din * w1g;
            xo += din * w1o;
        }

        const float ii = sigmoidf_(xi);
        const float ff = sigmoidf_(xf);
        const float gg = tanhf(xg);
        const float oo = sigmoidf_(xo);
        const float c  = ff * cR[q] + ii * gg;
        cR[q] = c;
        const float h = oo * tanhf(c);
        h_out[b * Hd + col] = h;

        if (MODE == 2) {
            float p = h * fcw;
#pragma unroll
            for (int off = 16; off > 0; off >>= 1)
                p += __shfl_xor_sync(0xFFFFFFFFu, p, off);
            if (pc == 0) g_fc_part[tileN][b] = p;
        }
    }
}

// ---------------- init kernel: per-replay reset + decoder seed ----------------
__global__ void init_kernel(const float* __restrict__ Xd) {
    const int tid = threadIdx.x;
    const int gid = blockIdx.x * blockDim.x + tid;
    const int total = 2 * Bq * Hd;
    float* h0 = &g_h0[0][0];
    float* h1 = &g_h1[0][0];
    for (int i = gid; i < total; i += gridDim.x * blockDim.x) {
        h0[i] = 0.0f;
        h1[i] = 0.0f;
    }
    if (gid == 0) g_bar = 0u;

    const int b = blockIdx.x;
    if (b < Bq) {
        float s = 0.0f;
        for (int i = tid; i < PRED * 8; i += blockDim.x) s += Xd[b * PRED * 8 + i];
        __shared__ float red[NTHR];
        red[tid] = s;
        __syncthreads();
        for (int off = NTHR / 2; off > 0; off >>= 1) {
            if (tid < off) red[tid] += red[tid + off];
            __syncthreads();
        }
        if (tid == 0) g_dec_in0[b] = red[0];
    }
}

// ---------------- persistent seq2seq kernel ----------------
__global__ __launch_bounds__(NTHR, 1) void seq2seq_kernel(
    const float* __restrict__ Xe,
    const float* __restrict__ y, const int* __restrict__ tfm,
    const float* __restrict__ eWi0, const float* __restrict__ eWh0,
    const float* __restrict__ ebi0, const float* __restrict__ ebh0,
    const float* __restrict__ eWi1, const float* __restrict__ eWh1,
    const float* __restrict__ ebi1, const float* __restrict__ ebh1,
    const float* __restrict__ dWi0, const float* __restrict__ dWh0,
    const float* __restrict__ dbi0, const float* __restrict__ dbh0,
    const float* __restrict__ dWi1, const float* __restrict__ dWh1,
    const float* __restrict__ dbi1, const float* __restrict__ dbh1,
    const float* __restrict__ fcW, const float* __restrict__ fcB,
    float* __restrict__ d_out) {
    __shared__ SM sm;

    const int tileM = blockIdx.x >> 4;   // 0..7
    const int tileN = blockIdx.x & 15;   // 0..15
    const int bm0 = tileM * BM;
    const int hc0 = tileN * 32;

    float c0r[8], c1r[8];
#pragma unroll
    for (int q = 0; q < 8; ++q) { c0r[q] = 0.0f; c1r[q] = 0.0f; }

    unsigned int phase = 0;
    int par = 0;
    float acc[4][8];

    // ---------------- encoder ----------------
    for (int t = 0; t < T_ENC; ++t) {
        float* hr0 = g_h0[par];
        float* hw0 = g_h0[par ^ 1];
        float* hr1 = g_h1[par];
        float* hw1 = g_h1[par ^ 1];

        // stage A: gates0 = h0 @ Whh0^T + x_t @ Wih0^T
#pragma unroll
        for (int i = 0; i < 4; ++i)
#pragma unroll
            for (int j = 0; j < 8; ++j) acc[i][j] = 0.0f;
        gemm_acc(acc, sm, hr0, Hd, eWh0, Hd, Hd, bm0, hc0);
        gemm_acc(acc, sm, Xe + t * FEAT, T_ENC * FEAT, eWi0, FEAT, FEAT, bm0, hc0);
        epilogue<0>(acc, sm, c0r, ebi0, ebh0, hw0, bm0, hc0, tileN,
                    nullptr, nullptr, nullptr, nullptr, t, nullptr, nullptr);
        grid_bar(&phase);

        // stage B: gates1 = h0_new @ Wih1^T + h1 @ Whh1^T
#pragma unroll
        for (int i = 0; i < 4; ++i)
#pragma unroll
            for (int j = 0; j < 8; ++j) acc[i][j] = 0.0f;
        gemm_acc(acc, sm, hw0, Hd, eWi1, Hd, Hd, bm0, hc0);
        gemm_acc(acc, sm, hr1, Hd, eWh1, Hd, Hd, bm0, hc0);
        epilogue<0>(acc, sm, c1r, ebi1, ebh1, hw1, bm0, hc0, tileN,
                    nullptr, nullptr, nullptr, nullptr, t, nullptr, nullptr);
        grid_bar(&phase);
        par ^= 1;
    }

    // ---------------- decoder ----------------
    for (int t = 0; t < PRED; ++t) {
        float* hr0 = g_h0[par];
        float* hw0 = g_h0[par ^ 1];
        float* hr1 = g_h1[par];
        float* hw1 = g_h1[par ^ 1];

        // stage A: gates0 = h0 @ dWhh0^T (+ din * dWih0 in epilogue)
#pragma unroll
        for (int i = 0; i < 4; ++i)
#pragma unroll
            for (int j = 0; j < 8; ++j) acc[i][j] = 0.0f;
        gemm_acc(acc, sm, hr0, Hd, dWh0, Hd, Hd, bm0, hc0);
        epilogue<1>(acc, sm, c0r, dbi0, dbh0, hw0, bm0, hc0, tileN,
                    dWi0, y, tfm, d_out, t, nullptr, fcB);
        grid_bar(&phase);

        // stage B
#pragma unroll
        for (int i = 0; i < 4; ++i)
#pragma unroll
            for (int j = 0; j < 8; ++j) acc[i][j] = 0.0f;
        gemm_acc(acc, sm, hw0, Hd, dWi1, Hd, Hd, bm0, hc0);
        gemm_acc(acc, sm, hr1, Hd, dWh1, Hd, Hd, bm0, hc0);
        epilogue<2>(acc, sm, c1r, dbi1, dbh1, hw1, bm0, hc0, tileN,
                    nullptr, nullptr, nullptr, nullptr, t, fcW, nullptr);
        grid_bar(&phase);
        par ^= 1;
    }

    // ---------------- final output (t = PRED-1) ----------------
    if (tileN == 0 && threadIdx.x < BM) {
        const int b = bm0 + threadIdx.x;
        float out = fcB[0];
#pragma unroll
        for (int j = 0; j < 16; ++j) out += g_fc_part[j][b];
        d_out[b * PRED + (PRED - 1)] = out;
    }
}

// ---------------- harness entry ----------------
extern "C" void kernel_launch(void* const* d_in, const int* in_sizes, int n_in,
                              void* d_out, int out_size) {
    const float* Xe  = (const float*)d_in[0];
    const float* Xd  = (const float*)d_in[1];
    const float* y   = (const float*)d_in[2];
    const int*   tfm = (const int*)d_in[3];
    const float* eWi0 = (const float*)d_in[4];
    const float* eWh0 = (const float*)d_in[5];
    const float* ebi0 = (const float*)d_in[6];
    const float* ebh0 = (const float*)d_in[7];
    const float* eWi1 = (const float*)d_in[8];
    const float* eWh1 = (const float*)d_in[9];
    const float* ebi1 = (const float*)d_in[10];
    const float* ebh1 = (const float*)d_in[11];
    const float* dWi0 = (const float*)d_in[12];
    const float* dWh0 = (const float*)d_in[13];
    const float* dbi0 = (const float*)d_in[14];
    const float* dbh0 = (const float*)d_in[15];
    const float* dWi1 = (const float*)d_in[16];
    const float* dWh1 = (const float*)d_in[17];
    const float* dbi1 = (const float*)d_in[18];
    const float* dbh1 = (const float*)d_in[19];
    const float* fcW  = (const float*)d_in[20];
    const float* fcB  = (const float*)d_in[21];
    float* out = (float*)d_out;

    init_kernel<<<512, NTHR>>>(Xd);
    seq2seq_kernel<<<GRIDSZ, NTHR>>>(Xe, y, tfm,
                                     eWi0, eWh0, ebi0, ebh0,
                                     eWi1, eWh1, ebi1, ebh1,
                                     dWi0, dWh0, dbi0, dbh0,
                                     dWi1, dWh1, dbi1, dbh1,
                                     fcW, fcB, out);
}

// round 3
// speedup vs baseline: 3.0868x; 3.0868x over previous
#include <cuda_runtime.h>
#include <cuda_bf16.h>
#include <cstdint>
#include <math.h>

typedef unsigned int u32;

// ---------------- problem constants ----------------
#define Bq     512
#define Hd     512
#define FEAT   128
#define T_ENC  512
#define PRED   96

#define GRIDSZ 128
#define NTHR   256
#define BM 64
#define BN 128
#define APAD 40   // padded smem row stride (bf16) for conflict-free ldmatrix

// ---------------- persistent device state ----------------
__device__ __nv_bfloat16 g_h0h[2][Bq * Hd], g_h0l[2][Bq * Hd];
__device__ __nv_bfloat16 g_h1h[2][Bq * Hd], g_h1l[2][Bq * Hd];
__device__ float g_fc_part[16][Bq];
__device__ float g_dec_in0[Bq];
__device__ unsigned int g_bar;

// split weights, permuted rows: P = tileN*128 + j, orig = (j/32)*512 + tileN*32 + (j%32)
__device__ __nv_bfloat16 g_eWh0h[2048 * 512], g_eWh0l[2048 * 512];
__device__ __nv_bfloat16 g_eWi0h[2048 * 128], g_eWi0l[2048 * 128];
__device__ __nv_bfloat16 g_eWi1h[2048 * 512], g_eWi1l[2048 * 512];
__device__ __nv_bfloat16 g_eWh1h[2048 * 512], g_eWh1l[2048 * 512];
__device__ __nv_bfloat16 g_dWh0h[2048 * 512], g_dWh0l[2048 * 512];
__device__ __nv_bfloat16 g_dWi1h[2048 * 512], g_dWi1l[2048 * 512];
__device__ __nv_bfloat16 g_dWh1h[2048 * 512], g_dWh1l[2048 * 512];
// split encoder input, original [b][t][f] layout
__device__ __nv_bfloat16 g_Xh[Bq * T_ENC * FEAT], g_Xl[Bq * T_ENC * FEAT];

struct SM {
    union {
        struct {
            __nv_bfloat16 Ah[BM][APAD], Al[BM][APAD];
            __nv_bfloat16 Wh[BN][APAD], Wl[BN][APAD];
        } ld;                                   // ~30 KB
        float gates[BM][BN];                    // 32 KB
    };
};

// ---------------- helpers ----------------
__device__ __forceinline__ u32 smem_u32(const void* p) {
    return (u32)__cvta_generic_to_shared(const_cast<void*>(p));
}
__device__ __forceinline__ void ldsm4(u32* r, u32 addr) {
    asm volatile("ldmatrix.sync.aligned.m8n8.x4.shared.b16 {%0,%1,%2,%3},[%4];"
                 : "=r"(r[0]), "=r"(r[1]), "=r"(r[2]), "=r"(r[3]) : "r"(addr));
}
__device__ __forceinline__ void mma16816(float* c, const u32* a, const u32* b) {
    asm volatile("mma.sync.aligned.m16n8k16.row.col.f32.bf16.bf16.f32 "
                 "{%0,%1,%2,%3},{%4,%5,%6,%7},{%8,%9},{%0,%1,%2,%3};"
                 : "+f"(c[0]), "+f"(c[1]), "+f"(c[2]), "+f"(c[3])
                 : "r"(a[0]), "r"(a[1]), "r"(a[2]), "r"(a[3]), "r"(b[0]), "r"(b[1]));
}
__device__ __forceinline__ float sigmoidf_(float x) { return 1.0f / (1.0f + expf(-x)); }

__device__ __forceinline__ void grid_bar(unsigned int* phase) {
    __syncthreads();
    if (threadIdx.x == 0) {
        __threadfence();
        atomicAdd(&g_bar, 1u);
        ++(*phase);
        const unsigned int target = (*phase) * (unsigned int)GRIDSZ;
        for (;;) {
            unsigned int v;
            asm volatile("ld.global.acquire.gpu.u32 %0, [%1];" : "=r"(v) : "l"(&g_bar));
            if (v >= target) break;
            __nanosleep(64);
        }
        __threadfence();
    }
    __syncthreads();
}

// ---------------- tensor-core GEMM: acc += split(A[64 x K]) * split(W)^T --------
// Wh/Wl pre-offset to this CTA's 128 permuted rows; row stride = K.
__device__ __forceinline__ void gemm_mma(float acc[8][4], SM& sm,
                                         const __nv_bfloat16* __restrict__ Ah,
                                         const __nv_bfloat16* __restrict__ Al, int lda,
                                         const __nv_bfloat16* __restrict__ Wh,
                                         const __nv_bfloat16* __restrict__ Wl,
                                         int K, int bm0) {
    const int tid = threadIdx.x;
    const int lane = tid & 31;
    const int wid = tid >> 5;
    const int wm = wid & 3, wn = wid >> 2;
    const int ar = tid >> 2;           // 0..63
    const int ak = (tid & 3) << 3;     // 0,8,16,24

    const __nv_bfloat16* gAh = Ah + (size_t)(bm0 + ar) * lda + ak;
    const __nv_bfloat16* gAl = Al + (size_t)(bm0 + ar) * lda + ak;
    const __nv_bfloat16* gWh0 = Wh + ar * K + ak;
    const __nv_bfloat16* gWh1 = Wh + (64 + ar) * K + ak;
    const __nv_bfloat16* gWl0 = Wl + ar * K + ak;
    const __nv_bfloat16* gWl1 = Wl + (64 + ar) * K + ak;

    uint4 pah = *(const uint4*)gAh;
    uint4 pal = *(const uint4*)gAl;
    uint4 pwh0 = *(const uint4*)gWh0;
    uint4 pwh1 = *(const uint4*)gWh1;
    uint4 pwl0 = *(const uint4*)gWl0;
    uint4 pwl1 = *(const uint4*)gWl1;

    // ldmatrix lane addressing
    const int q = lane >> 3, l7 = lane & 7;
    const int arow = wm * 16 + ((q & 1) << 3) + l7;
    const int acol = (q >> 1) << 3;
    const u32 aHaddr = smem_u32(&sm.ld.Ah[arow][acol]);
    const u32 aLaddr = smem_u32(&sm.ld.Al[arow][acol]);
    const int brow = ((q >> 1) << 3) + l7;
    const int bcol = (q & 1) << 3;
    u32 bHaddr[4], bLaddr[4];
#pragma unroll
    for (int p = 0; p < 4; ++p) {
        bHaddr[p] = smem_u32(&sm.ld.Wh[wn * 64 + p * 16 + brow][bcol]);
        bLaddr[p] = smem_u32(&sm.ld.Wl[wn * 64 + p * 16 + brow][bcol]);
    }

    for (int k0 = 32;; k0 += 32) {
        __syncthreads();
        *(uint4*)&sm.ld.Ah[ar][ak] = pah;
        *(uint4*)&sm.ld.Al[ar][ak] = pal;
        *(uint4*)&sm.ld.Wh[ar][ak] = pwh0;
        *(uint4*)&sm.ld.Wh[64 + ar][ak] = pwh1;
        *(uint4*)&sm.ld.Wl[ar][ak] = pwl0;
        *(uint4*)&sm.ld.Wl[64 + ar][ak] = pwl1;
        __syncthreads();
        if (k0 < K) {
            pah = *(const uint4*)(gAh + k0);
            pal = *(const uint4*)(gAl + k0);
            pwh0 = *(const uint4*)(gWh0 + k0);
            pwh1 = *(const uint4*)(gWh1 + k0);
            pwl0 = *(const uint4*)(gWl0 + k0);
            pwl1 = *(const uint4*)(gWl1 + k0);
        }
#pragma unroll
        for (int ks = 0; ks < 2; ++ks) {
            const u32 off = ks * 32;   // 16 bf16 = 32 bytes
            u32 a_h[4], a_l[4];
            ldsm4(a_h, aHaddr + off);
            ldsm4(a_l, aLaddr + off);
#pragma unroll
            for (int p = 0; p < 4; ++p) {
                u32 bh[4], bl[4];
                ldsm4(bh, bHaddr[p] + off);
                ldsm4(bl, bLaddr[p] + off);
                mma16816(acc[2 * p],     a_h, bh);
                mma16816(acc[2 * p + 1], a_h, bh + 2);
                mma16816(acc[2 * p],     a_h, bl);
                mma16816(acc[2 * p + 1], a_h, bl + 2);
                mma16816(acc[2 * p],     a_l, bh);
                mma16816(acc[2 * p + 1], a_l, bh + 2);
            }
        }
        if (k0 >= K) break;
    }
}

// ---------------- epilogue: bias + LSTM pointwise, h stored as bf16 hi/lo -------
template <int MODE>
__device__ __forceinline__ void epilogue(float acc[8][4], SM& sm, float cR[8],
                                         const float* __restrict__ b_ih,
                                         const float* __restrict__ b_hh,
                                         __nv_bfloat16* __restrict__ hH,
                                         __nv_bfloat16* __restrict__ hL,
                                         int bm0, int hc0, int tileN,
                                         const float* __restrict__ rank1w,
                                         const float* __restrict__ y,
                                         const int* __restrict__ tf_mask,
                                         float* __restrict__ d_out, int t,
                                         const float* __restrict__ fcW,
                                         const float* __restrict__ fc_b) {
    const int tid = threadIdx.x;
    const int lane = tid & 31, wid = tid >> 5;
    const int wm = wid & 3, wn = wid >> 2;

    __syncthreads();   // all ldmatrix reads done before aliasing ld-region with gates
    {
        const int r0 = wm * 16 + (lane >> 2);
        const int c0 = wn * 64 + ((lane & 3) << 1);
#pragma unroll
        for (int j = 0; j < 8; ++j) {
            *(float2*)&sm.gates[r0][c0 + j * 8]     = make_float2(acc[j][0], acc[j][1]);
            *(float2*)&sm.gates[r0 + 8][c0 + j * 8] = make_float2(acc[j][2], acc[j][3]);
        }
    }
    __syncthreads();

    const int pc  = tid & 31;
    const int pr0 = (tid >> 5) * 8;
    const int col = hc0 + pc;

    const float bi = b_ih[col]        + b_hh[col];
    const float bf = b_ih[512 + col]  + b_hh[512 + col];
    const float bg = b_ih[1024 + col] + b_hh[1024 + col];
    const float bo = b_ih[1536 + col] + b_hh[1536 + col];

    float w1i = 0.f, w1f = 0.f, w1g = 0.f, w1o = 0.f, fcw = 0.f;
    if (MODE == 1) {
        w1i = rank1w[col];
        w1f = rank1w[512 + col];
        w1g = rank1w[1024 + col];
        w1o = rank1w[1536 + col];
    }
    if (MODE == 2) fcw = fcW[col];

    const bool tfprev = (MODE == 1 && t > 0) ? (tf_mask[t - 1] != 0) : false;

#pragma unroll
    for (int qq = 0; qq < 8; ++qq) {
        const int r = pr0 + qq;
        const int b = bm0 + r;

        float xi = sm.gates[r][pc]      + bi;
        float xf = sm.gates[r][32 + pc] + bf;
        float xg = sm.gates[r][64 + pc] + bg;
        float xo = sm.gates[r][96 + pc] + bo;

        if (MODE == 1) {
            float din;
            if (t == 0) {
                din = g_dec_in0[b];
            } else {
                float out = fc_b[0];
#pragma unroll
                for (int j = 0; j < 16; ++j) out += g_fc_part[j][b];
                if (tileN == 0 && pc == 0) d_out[b * PRED + (t - 1)] = out;
                din = tfprev ? y[b * PRED + t] : out;
            }
            xi += din * w1i;
            xf += din * w1f;
            xg += din * w1g;
            xo += din * w1o;
        }

        const float ii = sigmoidf_(xi);
        const float ff = sigmoidf_(xf);
        const float gg = tanhf(xg);
        const float oo = sigmoidf_(xo);
        const float c  = ff * cR[qq] + ii * gg;
        cR[qq] = c;
        const float h = oo * tanhf(c);

        __nv_bfloat16 hh = __float2bfloat16(h);
        hH[b * Hd + col] = hh;
        hL[b * Hd + col] = __float2bfloat16(h - __bfloat162float(hh));

        if (MODE == 2) {
            float p = h * fcw;
#pragma unroll
            for (int off = 16; off > 0; off >>= 1)
                p += __shfl_xor_sync(0xFFFFFFFFu, p, off);
            if (pc == 0) g_fc_part[tileN][b] = p;
        }
    }
}

// ---------------- init: split weights/X, zero h, seed, reset barrier ------------
__device__ void split_w(__nv_bfloat16* dh, __nv_bfloat16* dl,
                        const float* __restrict__ src, int K, int gid, int stride) {
    const int total = 2048 * K;
    for (int i = gid; i < total; i += stride) {
        const int P = i / K, k = i - P * K;
        const int tn = P >> 7, j = P & 127;
        const int orig = ((j >> 5) << 9) + (tn << 5) + (j & 31);
        const float v = src[orig * K + k];
        const __nv_bfloat16 hh = __float2bfloat16(v);
        dh[i] = hh;
        dl[i] = __float2bfloat16(v - __bfloat162float(hh));
    }
}

__global__ void init_kernel(const float* __restrict__ Xd, const float* __restrict__ Xe,
                            const float* __restrict__ eWi0, const float* __restrict__ eWh0,
                            const float* __restrict__ eWi1, const float* __restrict__ eWh1,
                            const float* __restrict__ dWh0, const float* __restrict__ dWi1,
                            const float* __restrict__ dWh1) {
    const int tid = threadIdx.x;
    const int gid = blockIdx.x * blockDim.x + tid;
    const int stride = gridDim.x * blockDim.x;

    // zero h buffer 0 (hi/lo, both layers)
    for (int i = gid; i < Bq * Hd; i += stride) {
        g_h0h[0][i] = __float2bfloat16(0.f);
        g_h0l[0][i] = __float2bfloat16(0.f);
        g_h1h[0][i] = __float2bfloat16(0.f);
        g_h1l[0][i] = __float2bfloat16(0.f);
    }
    if (gid == 0) g_bar = 0u;

    // split X_encode
    {
        const int total = Bq * T_ENC * FEAT;
        for (int i = gid; i < total; i += stride) {
            const float v = Xe[i];
            const __nv_bfloat16 hh = __float2bfloat16(v);
            g_Xh[i] = hh;
            g_Xl[i] = __float2bfloat16(v - __bfloat162float(hh));
        }
    }

    // split + permute weights
    split_w(g_eWh0h, g_eWh0l, eWh0, 512, gid, stride);
    split_w(g_eWi0h, g_eWi0l, eWi0, 128, gid, stride);
    split_w(g_eWi1h, g_eWi1l, eWi1, 512, gid, stride);
    split_w(g_eWh1h, g_eWh1l, eWh1, 512, gid, stride);
    split_w(g_dWh0h, g_dWh0l, dWh0, 512, gid, stride);
    split_w(g_dWi1h, g_dWi1l, dWi1, 512, gid, stride);
    split_w(g_dWh1h, g_dWh1l, dWh1, 512, gid, stride);

    // decoder seed: sum over X_decode per batch
    const int b = blockIdx.x;
    if (b < Bq) {
        float s = 0.0f;
        for (int i = tid; i < PRED * 8; i += blockDim.x) s += Xd[b * PRED * 8 + i];
        __shared__ float red[NTHR];
        red[tid] = s;
        __syncthreads();
        for (int off = NTHR / 2; off > 0; off >>= 1) {
            if (tid < off) red[tid] += red[tid + off];
            __syncthreads();
        }
        if (tid == 0) g_dec_in0[b] = red[0];
    }
}

// ---------------- persistent seq2seq kernel ----------------
__global__ __launch_bounds__(NTHR, 1) void seq2seq_kernel(
    const float* __restrict__ y, const int* __restrict__ tfm,
    const float* __restrict__ ebi0, const float* __restrict__ ebh0,
    const float* __restrict__ ebi1, const float* __restrict__ ebh1,
    const float* __restrict__ dWi0,
    const float* __restrict__ dbi0, const float* __restrict__ dbh0,
    const float* __restrict__ dbi1, const float* __restrict__ dbh1,
    const float* __restrict__ fcW, const float* __restrict__ fcB,
    float* __restrict__ d_out) {
    __shared__ SM sm;

    const int tileM = blockIdx.x >> 4;   // 0..7
    const int tileN = blockIdx.x & 15;   // 0..15
    const int bm0 = tileM * BM;
    const int hc0 = tileN * 32;
    const int woff512 = tileN * 128 * 512;  // permuted W row offset for K=512
    const int woff128 = tileN * 128 * 128;

    float c0r[8], c1r[8];
#pragma unroll
    for (int qq = 0; qq < 8; ++qq) { c0r[qq] = 0.0f; c1r[qq] = 0.0f; }

    unsigned int phase = 0;
    int par = 0;
    float acc[8][4];

    // ---------------- encoder ----------------
    for (int t = 0; t < T_ENC; ++t) {
        const __nv_bfloat16* hr0h = g_h0h[par];
        const __nv_bfloat16* hr0l = g_h0l[par];
        __nv_bfloat16* hw0h = g_h0h[par ^ 1];
        __nv_bfloat16* hw0l = g_h0l[par ^ 1];
        const __nv_bfloat16* hr1h = g_h1h[par];
        const __nv_bfloat16* hr1l = g_h1l[par];
        __nv_bfloat16* hw1h = g_h1h[par ^ 1];
        __nv_bfloat16* hw1l = g_h1l[par ^ 1];

        // stage A: gates0 = h0 @ eWh0^T + x_t @ eWi0^T
#pragma unroll
        for (int i = 0; i < 8; ++i)
#pragma unroll
            for (int j = 0; j < 4; ++j) acc[i][j] = 0.0f;
        gemm_mma(acc, sm, hr0h, hr0l, Hd, g_eWh0h + woff512, g_eWh0l + woff512, 512, bm0);
        gemm_mma(acc, sm, g_Xh + t * FEAT, g_Xl + t * FEAT, T_ENC * FEAT,
                 g_eWi0h + woff128, g_eWi0l + woff128, 128, bm0);
        epilogue<0>(acc, sm, c0r, ebi0, ebh0, hw0h, hw0l, bm0, hc0, tileN,
                    (const float*)0, (const float*)0, (const int*)0, (float*)0, t,
                    (const float*)0, (const float*)0);
        grid_bar(&phase);

        // stage B: gates1 = h0_new @ eWi1^T + h1 @ eWh1^T
#pragma unroll
        for (int i = 0; i < 8; ++i)
#pragma unroll
            for (int j = 0; j < 4; ++j) acc[i][j] = 0.0f;
        gemm_mma(acc, sm, hw0h, hw0l, Hd, g_eWi1h + woff512, g_eWi1l + woff512, 512, bm0);
        gemm_mma(acc, sm, hr1h, hr1l, Hd, g_eWh1h + woff512, g_eWh1l + woff512, 512, bm0);
        epilogue<0>(acc, sm, c1r, ebi1, ebh1, hw1h, hw1l, bm0, hc0, tileN,
                    (const float*)0, (const float*)0, (const int*)0, (float*)0, t,
                    (const float*)0, (const float*)0);
        grid_bar(&phase);
        par ^= 1;
    }

    // ---------------- decoder ----------------
    for (int t = 0; t < PRED; ++t) {
        const __nv_bfloat16* hr0h = g_h0h[par];
        const __nv_bfloat16* hr0l = g_h0l[par];
        __nv_bfloat16* hw0h = g_h0h[par ^ 1];
        __nv_bfloat16* hw0l = g_h0l[par ^ 1];
        const __nv_bfloat16* hr1h = g_h1h[par];
        const __nv_bfloat16* hr1l = g_h1l[par];
        __nv_bfloat16* hw1h = g_h1h[par ^ 1];
        __nv_bfloat16* hw1l = g_h1l[par ^ 1];

        // stage A: gates0 = h0 @ dWh0^T  (+ din * dWi0 in epilogue)
#pragma unroll
        for (int i = 0; i < 8; ++i)
#pragma unroll
            for (int j = 0; j < 4; ++j) acc[i][j] = 0.0f;
        gemm_mma(acc, sm, hr0h, hr0l, Hd, g_dWh0h + woff512, g_dWh0l + woff512, 512, bm0);
        epilogue<1>(acc, sm, c0r, dbi0, dbh0, hw0h, hw0l, bm0, hc0, tileN,
                    dWi0, y, tfm, d_out, t, (const float*)0, fcB);
        grid_bar(&phase);

        // stage B
#pragma unroll
        for (int i = 0; i < 8; ++i)
#pragma unroll
            for (int j = 0; j < 4; ++j) acc[i][j] = 0.0f;
        gemm_mma(acc, sm, hw0h, hw0l, Hd, g_dWi1h + woff512, g_dWi1l + woff512, 512, bm0);
        gemm_mma(acc, sm, hr1h, hr1l, Hd, g_dWh1h + woff512, g_dWh1l + woff512, 512, bm0);
        epilogue<2>(acc, sm, c1r, dbi1, dbh1, hw1h, hw1l, bm0, hc0, tileN,
                    (const float*)0, (const float*)0, (const int*)0, (float*)0, t,
                    fcW, (const float*)0);
        grid_bar(&phase);
        par ^= 1;
    }

    // ---------------- final output (t = PRED-1) ----------------
    if (tileN == 0 && threadIdx.x < BM) {
        const int b = bm0 + threadIdx.x;
        float out = fcB[0];
#pragma unroll
        for (int j = 0; j < 16; ++j) out += g_fc_part[j][b];
        d_out[b * PRED + (PRED - 1)] = out;
    }
}

// ---------------- harness entry ----------------
extern "C" void kernel_launch(void* const* d_in, const int* in_sizes, int n_in,
                              void* d_out, int out_size) {
    const float* Xe  = (const float*)d_in[0];
    const float* Xd  = (const float*)d_in[1];
    const float* y   = (const float*)d_in[2];
    const int*   tfm = (const int*)d_in[3];
    const float* eWi0 = (const float*)d_in[4];
    const float* eWh0 = (const float*)d_in[5];
    const float* ebi0 = (const float*)d_in[6];
    const float* ebh0 = (const float*)d_in[7];
    const float* eWi1 = (const float*)d_in[8];
    const float* eWh1 = (const float*)d_in[9];
    const float* ebi1 = (const float*)d_in[10];
    const float* ebh1 = (const float*)d_in[11];
    const float* dWi0 = (const float*)d_in[12];
    const float* dWh0 = (const float*)d_in[13];
    const float* dbi0 = (const float*)d_in[14];
    const float* dbh0 = (const float*)d_in[15];
    const float* dWi1 = (const float*)d_in[16];
    const float* dWh1 = (const float*)d_in[17];
    const float* dbi1 = (const float*)d_in[18];
    const float* dbh1 = (const float*)d_in[19];
    const float* fcW  = (const float*)d_in[20];
    const float* fcB  = (const float*)d_in[21];
    float* out = (float*)d_out;

    init_kernel<<<1024, NTHR>>>(Xd, Xe, eWi0, eWh0, eWi1, eWh1, dWh0, dWi1, dWh1);
    seq2seq_kernel<<<GRIDSZ, NTHR>>>(y, tfm,
                                     ebi0, ebh0, ebi1, ebh1,
                                     dWi0, dbi0, dbh0, dbi1, dbh1,
                                     fcW, fcB, out);
}

// round 4
// speedup vs baseline: 3.6585x; 1.1852x over previous
#include <cuda_runtime.h>
#include <cuda_bf16.h>
#include <cstdint>
#include <math.h>

typedef unsigned int u32;

// ---------------- problem constants ----------------
#define Bq     512
#define Hd     512
#define FEAT   128
#define T_ENC  512
#define PRED   96

#define GRIDSZ 128
#define NTHR   256
#define BM 64
#define BN 128
#define APAD 40              // padded smem row stride (bf16): 80B, 16B-aligned, conflict-free

// ---------------- persistent device state ----------------
__device__ __nv_bfloat16 g_h0h[2][Bq * Hd], g_h0l[2][Bq * Hd];
__device__ __nv_bfloat16 g_h1h[2][Bq * Hd], g_h1l[2][Bq * Hd];
__device__ float g_fc_part[16][Bq];
__device__ float g_dec_in0[Bq];
__device__ unsigned int g_bar;

// split weights, permuted rows: P = tileN*128 + j, orig = (j/32)*512 + tileN*32 + (j%32)
__device__ __nv_bfloat16 g_eWh0h[2048 * 512], g_eWh0l[2048 * 512];
__device__ __nv_bfloat16 g_eWi0h[2048 * 128], g_eWi0l[2048 * 128];
__device__ __nv_bfloat16 g_eWi1h[2048 * 512], g_eWi1l[2048 * 512];
__device__ __nv_bfloat16 g_eWh1h[2048 * 512], g_eWh1l[2048 * 512];
__device__ __nv_bfloat16 g_dWh0h[2048 * 512], g_dWh0l[2048 * 512];
__device__ __nv_bfloat16 g_dWi1h[2048 * 512], g_dWi1l[2048 * 512];
__device__ __nv_bfloat16 g_dWh1h[2048 * 512], g_dWh1l[2048 * 512];
__device__ __nv_bfloat16 g_Xh[Bq * T_ENC * FEAT], g_Xl[Bq * T_ENC * FEAT];

// ---------------- smem layout (dynamic) ----------------
struct Chunk {
    __nv_bfloat16 Ah[BM][APAD];
    __nv_bfloat16 Al[BM][APAD];
    __nv_bfloat16 Wh[BN][APAD];
    __nv_bfloat16 Wl[BN][APAD];
};                                   // 30720 B
#define CHB 30720u
struct SM {
    union {
        Chunk ch[2];                 // 61440 B
        float gates[BM][BN];         // 32768 B
    };
};
#define SMEM_BYTES 61440

// ---------------- helpers ----------------
__device__ __forceinline__ u32 smem_u32(const void* p) {
    return (u32)__cvta_generic_to_shared(const_cast<void*>(p));
}
__device__ __forceinline__ void ldsm4(u32* r, u32 addr) {
    asm volatile("ldmatrix.sync.aligned.m8n8.x4.shared.b16 {%0,%1,%2,%3},[%4];"
                 : "=r"(r[0]), "=r"(r[1]), "=r"(r[2]), "=r"(r[3]) : "r"(addr));
}
__device__ __forceinline__ void mma16816(float* c, const u32* a, const u32* b) {
    asm volatile("mma.sync.aligned.m16n8k16.row.col.f32.bf16.bf16.f32 "
                 "{%0,%1,%2,%3},{%4,%5,%6,%7},{%8,%9},{%0,%1,%2,%3};"
                 : "+f"(c[0]), "+f"(c[1]), "+f"(c[2]), "+f"(c[3])
                 : "r"(a[0]), "r"(a[1]), "r"(a[2]), "r"(a[3]), "r"(b[0]), "r"(b[1]));
}
#define CP16(d, s)  asm volatile("cp.async.cg.shared.global [%0], [%1], 16;" :: "r"(d), "l"(s) : "memory")
#define CPCOMMIT()  asm volatile("cp.async.commit_group;" ::: "memory")
#define CPWAIT0()   asm volatile("cp.async.wait_group 0;" ::: "memory")
#define CPWAIT1()   asm volatile("cp.async.wait_group 1;" ::: "memory")

__device__ __forceinline__ float sigmoidf_(float x) { return 1.0f / (1.0f + expf(-x)); }

__device__ __forceinline__ void grid_bar(unsigned int* phase) {
    __syncthreads();
    if (threadIdx.x == 0) {
        __threadfence();
        atomicAdd(&g_bar, 1u);
        ++(*phase);
        const unsigned int target = (*phase) * (unsigned int)GRIDSZ;
        for (;;) {
            unsigned int v;
            asm volatile("ld.global.acquire.gpu.u32 %0, [%1];" : "=r"(v) : "l"(&g_bar));
            if (v >= target) break;
            __nanosleep(64);
        }
        __threadfence();
    }
    __syncthreads();
}

// ---------------- tensor-core GEMM (cp.async double-buffered) ------------------
// acc[m16-block][n8-frag][4]; warp tile m32n32 (wm=wid&1, wn=wid>>1).
__device__ __forceinline__ void gemm_async(float acc[2][4][4], SM& sm,
        const __nv_bfloat16* __restrict__ Ah, const __nv_bfloat16* __restrict__ Al,
        size_t lda,
        const __nv_bfloat16* __restrict__ Wh, const __nv_bfloat16* __restrict__ Wl,
        int K, int bm0)
{
    const int tid = threadIdx.x, lane = tid & 31, wid = tid >> 5;
    const int wm = wid & 1, wn = wid >> 1;

    // cp.async load mapping: A 64x32 (1 seg each), W 128x32 (2 segs each)
    const int ar = tid >> 2, ac = (tid & 3) << 3;
    const int wr = tid >> 2, wc = (tid & 3) << 3;

    const __nv_bfloat16* gAh  = Ah + (size_t)(bm0 + ar) * lda + ac;
    const __nv_bfloat16* gAl  = Al + (size_t)(bm0 + ar) * lda + ac;
    const __nv_bfloat16* gWh0 = Wh + wr * K + wc;
    const __nv_bfloat16* gWh1 = Wh + (wr + 64) * K + wc;
    const __nv_bfloat16* gWl0 = Wl + wr * K + wc;
    const __nv_bfloat16* gWl1 = Wl + (wr + 64) * K + wc;

    const u32 sA_h  = smem_u32(&sm.ch[0].Ah[ar][ac]);
    const u32 sA_l  = smem_u32(&sm.ch[0].Al[ar][ac]);
    const u32 sW_h0 = smem_u32(&sm.ch[0].Wh[wr][wc]);
    const u32 sW_h1 = smem_u32(&sm.ch[0].Wh[wr + 64][wc]);
    const u32 sW_l0 = smem_u32(&sm.ch[0].Wl[wr][wc]);
    const u32 sW_l1 = smem_u32(&sm.ch[0].Wl[wr + 64][wc]);

    // ldmatrix addressing (buffer 0 base; add (c&1)*CHB per chunk)
    const int q = lane >> 3, l7 = lane & 7;
    const int arow = ((q & 1) << 3) + l7, acol = (q >> 1) << 3;
    const int brow = ((q >> 1) << 3) + l7, bcol = (q & 1) << 3;
    const u32 aH0 = smem_u32(&sm.ch[0].Ah[wm * 32 + arow][acol]);
    const u32 aH1 = smem_u32(&sm.ch[0].Ah[wm * 32 + 16 + arow][acol]);
    const u32 aL0 = smem_u32(&sm.ch[0].Al[wm * 32 + arow][acol]);
    const u32 aL1 = smem_u32(&sm.ch[0].Al[wm * 32 + 16 + arow][acol]);
    const u32 bH0 = smem_u32(&sm.ch[0].Wh[wn * 32 + brow][bcol]);
    const u32 bH1 = smem_u32(&sm.ch[0].Wh[wn * 32 + 16 + brow][bcol]);
    const u32 bL0 = smem_u32(&sm.ch[0].Wl[wn * 32 + brow][bcol]);
    const u32 bL1 = smem_u32(&sm.ch[0].Wl[wn * 32 + 16 + brow][bcol]);

    const int nc = K >> 5;

    __syncthreads();   // prior smem consumers (gates / previous gemm) done

    // prologue: chunks 0 and 1
    CP16(sA_h, gAh); CP16(sA_l, gAl);
    CP16(sW_h0, gWh0); CP16(sW_h1, gWh1);
    CP16(sW_l0, gWl0); CP16(sW_l1, gWl1);
    CPCOMMIT();
    CP16(sA_h + CHB, gAh + 32); CP16(sA_l + CHB, gAl + 32);
    CP16(sW_h0 + CHB, gWh0 + 32); CP16(sW_h1 + CHB, gWh1 + 32);
    CP16(sW_l0 + CHB, gWl0 + 32); CP16(sW_l1 + CHB, gWl1 + 32);
    CPCOMMIT();

    for (int c = 0; c < nc; ++c) {
        if (c + 1 < nc) { CPWAIT1(); } else { CPWAIT0(); }
        __syncthreads();
        const u32 cofs = (u32)(c & 1) * CHB;
#pragma unroll
        for (int ks = 0; ks < 2; ++ks) {
            const u32 off = cofs + ks * 32;
            u32 rah0[4], rah1[4], ral0[4], ral1[4];
            u32 rbh0[4], rbh1[4], rbl0[4], rbl1[4];
            ldsm4(rah0, aH0 + off); ldsm4(rah1, aH1 + off);
            ldsm4(ral0, aL0 + off); ldsm4(ral1, aL1 + off);
            ldsm4(rbh0, bH0 + off); ldsm4(rbh1, bH1 + off);
            ldsm4(rbl0, bL0 + off); ldsm4(rbl1, bL1 + off);

            mma16816(acc[0][0], rah0, rbh0); mma16816(acc[0][1], rah0, rbh0 + 2);
            mma16816(acc[0][2], rah0, rbh1); mma16816(acc[0][3], rah0, rbh1 + 2);
            mma16816(acc[1][0], rah1, rbh0); mma16816(acc[1][1], rah1, rbh0 + 2);
            mma16816(acc[1][2], rah1, rbh1); mma16816(acc[1][3], rah1, rbh1 + 2);

            mma16816(acc[0][0], rah0, rbl0); mma16816(acc[0][1], rah0, rbl0 + 2);
            mma16816(acc[0][2], rah0, rbl1); mma16816(acc[0][3], rah0, rbl1 + 2);
            mma16816(acc[1][0], rah1, rbl0); mma16816(acc[1][1], rah1, rbl0 + 2);
            mma16816(acc[1][2], rah1, rbl1); mma16816(acc[1][3], rah1, rbl1 + 2);

            mma16816(acc[0][0], ral0, rbh0); mma16816(acc[0][1], ral0, rbh0 + 2);
            mma16816(acc[0][2], ral0, rbh1); mma16816(acc[0][3], ral0, rbh1 + 2);
            mma16816(acc[1][0], ral1, rbh0); mma16816(acc[1][1], ral1, rbh0 + 2);
            mma16816(acc[1][2], ral1, rbh1); mma16816(acc[1][3], ral1, rbh1 + 2);
        }
        __syncthreads();
        if (c + 2 < nc) {
            const int k0 = (c + 2) << 5;
            CP16(sA_h + cofs, gAh + k0); CP16(sA_l + cofs, gAl + k0);
            CP16(sW_h0 + cofs, gWh0 + k0); CP16(sW_h1 + cofs, gWh1 + k0);
            CP16(sW_l0 + cofs, gWl0 + k0); CP16(sW_l1 + cofs, gWl1 + k0);
            CPCOMMIT();
        }
    }
}

// ---------------- epilogue: bias + LSTM pointwise ------------------------------
template <int MODE>
__device__ __forceinline__ void epilogue(float acc[2][4][4], SM& sm, float cR[8],
                                         const float* __restrict__ b_ih,
                                         const float* __restrict__ b_hh,
                                         __nv_bfloat16* __restrict__ hH,
                                         __nv_bfloat16* __restrict__ hL,
                                         int bm0, int hc0, int tileN,
                                         const float* __restrict__ rank1w,
                                         const float* __restrict__ y,
                                         const int* __restrict__ tf_mask,
                                         float* __restrict__ d_out, int t,
                                         const float* __restrict__ fcW,
                                         const float* __restrict__ fc_b) {
    const int tid = threadIdx.x;
    const int lane = tid & 31, wid = tid >> 5;
    const int wm = wid & 1, wn = wid >> 1;

    __syncthreads();   // all ldsm reads done before aliasing ld-region with gates
    {
        const int r0 = wm * 32 + (lane >> 2);
        const int c0 = wn * 32 + ((lane & 3) << 1);
#pragma unroll
        for (int m = 0; m < 2; ++m)
#pragma unroll
            for (int j = 0; j < 4; ++j) {
                *(float2*)&sm.gates[r0 + m * 16][c0 + j * 8] =
                    make_float2(acc[m][j][0], acc[m][j][1]);
                *(float2*)&sm.gates[r0 + m * 16 + 8][c0 + j * 8] =
                    make_float2(acc[m][j][2], acc[m][j][3]);
            }
    }
    __syncthreads();

    const int pc  = tid & 31;
    const int pr0 = (tid >> 5) * 8;
    const int col = hc0 + pc;

    const float bi = b_ih[col]        + b_hh[col];
    const float bf = b_ih[512 + col]  + b_hh[512 + col];
    const float bg = b_ih[1024 + col] + b_hh[1024 + col];
    const float bo = b_ih[1536 + col] + b_hh[1536 + col];

    float w1i = 0.f, w1f = 0.f, w1g = 0.f, w1o = 0.f, fcw = 0.f;
    if (MODE == 1) {
        w1i = rank1w[col];
        w1f = rank1w[512 + col];
        w1g = rank1w[1024 + col];
        w1o = rank1w[1536 + col];
    }
    if (MODE == 2) fcw = fcW[col];

    const bool tfprev = (MODE == 1 && t > 0) ? (tf_mask[t - 1] != 0) : false;

#pragma unroll
    for (int qq = 0; qq < 8; ++qq) {
        const int r = pr0 + qq;
        const int b = bm0 + r;

        float xi = sm.gates[r][pc]      + bi;
        float xf = sm.gates[r][32 + pc] + bf;
        float xg = sm.gates[r][64 + pc] + bg;
        float xo = sm.gates[r][96 + pc] + bo;

        if (MODE == 1) {
            float din;
            if (t == 0) {
                din = g_dec_in0[b];
            } else {
                float out = fc_b[0];
#pragma unroll
                for (int j = 0; j < 16; ++j) out += g_fc_part[j][b];
                if (tileN == 0 && pc == 0) d_out[b * PRED + (t - 1)] = out;
                din = tfprev ? y[b * PRED + t] : out;
            }
            xi += din * w1i;
            xf += din * w1f;
            xg += din * w1g;
            xo += din * w1o;
        }

        const float ii = sigmoidf_(xi);
        const float ff = sigmoidf_(xf);
        const float gg = tanhf(xg);
        const float oo = sigmoidf_(xo);
        const float c  = ff * cR[qq] + ii * gg;
        cR[qq] = c;
        const float h = oo * tanhf(c);

        __nv_bfloat16 hh = __float2bfloat16(h);
        hH[b * Hd + col] = hh;
        hL[b * Hd + col] = __float2bfloat16(h - __bfloat162float(hh));

        if (MODE == 2) {
            float p = h * fcw;
#pragma unroll
            for (int off = 16; off > 0; off >>= 1)
                p += __shfl_xor_sync(0xFFFFFFFFu, p, off);
            if (pc == 0) g_fc_part[tileN][b] = p;
        }
    }
}

// ---------------- init: split weights/X, zero h (both buffers), seed -----------
__device__ void split_w(__nv_bfloat16* dh, __nv_bfloat16* dl,
                        const float* __restrict__ src, int K, int gid, int stride) {
    const int total = 2048 * K;
    for (int i = gid; i < total; i += stride) {
        const int P = i / K, k = i - P * K;
        const int tn = P >> 7, j = P & 127;
        const int orig = ((j >> 5) << 9) + (tn << 5) + (j & 31);
        const float v = src[orig * K + k];
        const __nv_bfloat16 hh = __float2bfloat16(v);
        dh[i] = hh;
        dl[i] = __float2bfloat16(v - __bfloat162float(hh));
    }
}

__global__ void init_kernel(const float* __restrict__ Xd, const float* __restrict__ Xe,
                            const float* __restrict__ eWi0, const float* __restrict__ eWh0,
                            const float* __restrict__ eWi1, const float* __restrict__ eWh1,
                            const float* __restrict__ dWh0, const float* __restrict__ dWi1,
                            const float* __restrict__ dWh1) {
    const int tid = threadIdx.x;
    const int gid = blockIdx.x * blockDim.x + tid;
    const int stride = gridDim.x * blockDim.x;

    const __nv_bfloat16 z = __float2bfloat16(0.f);
    for (int i = gid; i < Bq * Hd; i += stride) {
        g_h0h[0][i] = z; g_h0h[1][i] = z;
        g_h0l[0][i] = z; g_h0l[1][i] = z;
        g_h1h[0][i] = z; g_h1h[1][i] = z;
        g_h1l[0][i] = z; g_h1l[1][i] = z;
    }
    if (gid == 0) g_bar = 0u;

    {
        const int total = Bq * T_ENC * FEAT;
        for (int i = gid; i < total; i += stride) {
            const float v = Xe[i];
            const __nv_bfloat16 hh = __float2bfloat16(v);
            g_Xh[i] = hh;
            g_Xl[i] = __float2bfloat16(v - __bfloat162float(hh));
        }
    }

    split_w(g_eWh0h, g_eWh0l, eWh0, 512, gid, stride);
    split_w(g_eWi0h, g_eWi0l, eWi0, 128, gid, stride);
    split_w(g_eWi1h, g_eWi1l, eWi1, 512, gid, stride);
    split_w(g_eWh1h, g_eWh1l, eWh1, 512, gid, stride);
    split_w(g_dWh0h, g_dWh0l, dWh0, 512, gid, stride);
    split_w(g_dWi1h, g_dWi1l, dWi1, 512, gid, stride);
    split_w(g_dWh1h, g_dWh1l, dWh1, 512, gid, stride);

    const int b = blockIdx.x;
    if (b < Bq) {
        float s = 0.0f;
        for (int i = tid; i < PRED * 8; i += blockDim.x) s += Xd[b * PRED * 8 + i];
        __shared__ float red[NTHR];
        red[tid] = s;
        __syncthreads();
        for (int off = NTHR / 2; off > 0; off >>= 1) {
            if (tid < off) red[tid] += red[tid + off];
            __syncthreads();
        }
        if (tid == 0) g_dec_in0[b] = red[0];
    }
}

// ---------------- persistent seq2seq kernel ----------------
__global__ __launch_bounds__(NTHR, 1) void seq2seq_kernel(
    const float* __restrict__ y, const int* __restrict__ tfm,
    const float* __restrict__ ebi0, const float* __restrict__ ebh0,
    const float* __restrict__ ebi1, const float* __restrict__ ebh1,
    const float* __restrict__ dWi0,
    const float* __restrict__ dbi0, const float* __restrict__ dbh0,
    const float* __restrict__ dbi1, const float* __restrict__ dbh1,
    const float* __restrict__ fcW, const float* __restrict__ fcB,
    float* __restrict__ d_out) {
    extern __shared__ char s_raw[];
    SM& sm = *reinterpret_cast<SM*>(s_raw);

    const int tileM = blockIdx.x >> 4;   // 0..7
    const int tileN = blockIdx.x & 15;   // 0..15
    const int bm0 = tileM * BM;
    const int hc0 = tileN * 32;
    const size_t woff512 = (size_t)tileN * 128 * 512;
    const size_t woff128 = (size_t)tileN * 128 * 128;

    float c0r[8], c1r[8];
#pragma unroll
    for (int qq = 0; qq < 8; ++qq) { c0r[qq] = 0.0f; c1r[qq] = 0.0f; }

    unsigned int phase = 0;
    int par = 0;
    float acc[2][4][4];

#define ZERO_ACC() do { _Pragma("unroll") for (int _m = 0; _m < 2; ++_m) \
    _Pragma("unroll") for (int _j = 0; _j < 4; ++_j) \
    _Pragma("unroll") for (int _k = 0; _k < 4; ++_k) acc[_m][_j][_k] = 0.0f; } while (0)

    // ---------------- encoder (wavefront: layer0(t=s) + layer1(t=s-1)) ----------
    for (int s = 0; s < T_ENC; ++s) {
        const __nv_bfloat16* hr0h = g_h0h[par];
        const __nv_bfloat16* hr0l = g_h0l[par];
        __nv_bfloat16* hw0h = g_h0h[par ^ 1];
        __nv_bfloat16* hw0l = g_h0l[par ^ 1];
        const __nv_bfloat16* hr1h = g_h1h[par];
        const __nv_bfloat16* hr1l = g_h1l[par];
        __nv_bfloat16* hw1h = g_h1h[par ^ 1];
        __nv_bfloat16* hw1l = g_h1l[par ^ 1];

        // layer0(t=s): gates0 = h0(s-1) @ eWh0^T + x_s @ eWi0^T
        ZERO_ACC();
        gemm_async(acc, sm, hr0h, hr0l, Hd, g_eWh0h + woff512, g_eWh0l + woff512, 512, bm0);
        gemm_async(acc, sm, g_Xh + (size_t)s * FEAT, g_Xl + (size_t)s * FEAT,
                   (size_t)T_ENC * FEAT, g_eWi0h + woff128, g_eWi0l + woff128, 128, bm0);
        epilogue<0>(acc, sm, c0r, ebi0, ebh0, hw0h, hw0l, bm0, hc0, tileN,
                    (const float*)0, (const float*)0, (const int*)0, (float*)0, s,
                    (const float*)0, (const float*)0);

        // layer1(t=s-1): gates1 = h0(s-1) @ eWi1^T + h1(s-2) @ eWh1^T
        if (s > 0) {
            ZERO_ACC();
            gemm_async(acc, sm, hr0h, hr0l, Hd, g_eWi1h + woff512, g_eWi1l + woff512, 512, bm0);
            gemm_async(acc, sm, hr1h, hr1l, Hd, g_eWh1h + woff512, g_eWh1l + woff512, 512, bm0);
            epilogue<0>(acc, sm, c1r, ebi1, ebh1, hw1h, hw1l, bm0, hc0, tileN,
                        (const float*)0, (const float*)0, (const int*)0, (float*)0, s,
                        (const float*)0, (const float*)0);
        }
        grid_bar(&phase);
        par ^= 1;
    }

    // tail stage: layer1(t=T_ENC-1), plus copy final h0 across double buffer
    {
        const __nv_bfloat16* hr0h = g_h0h[par];
        const __nv_bfloat16* hr0l = g_h0l[par];
        __nv_bfloat16* hw0h = g_h0h[par ^ 1];
        __nv_bfloat16* hw0l = g_h0l[par ^ 1];
        const __nv_bfloat16* hr1h = g_h1h[par];
        const __nv_bfloat16* hr1l = g_h1l[par];
        __nv_bfloat16* hw1h = g_h1h[par ^ 1];
        __nv_bfloat16* hw1l = g_h1l[par ^ 1];

        ZERO_ACC();
        gemm_async(acc, sm, hr0h, hr0l, Hd, g_eWi1h + woff512, g_eWi1l + woff512, 512, bm0);
        gemm_async(acc, sm, hr1h, hr1l, Hd, g_eWh1h + woff512, g_eWh1l + woff512, 512, bm0);
        epilogue<0>(acc, sm, c1r, ebi1, ebh1, hw1h, hw1l, bm0, hc0, tileN,
                    (const float*)0, (const float*)0, (const int*)0, (float*)0, T_ENC,
                    (const float*)0, (const float*)0);

        for (int i = threadIdx.x; i < BM * 32; i += NTHR) {
            const int r = bm0 + (i >> 5), cc = hc0 + (i & 31);
            hw0h[r * Hd + cc] = hr0h[r * Hd + cc];
            hw0l[r * Hd + cc] = hr0l[r * Hd + cc];
        }
        grid_bar(&phase);
        par ^= 1;
    }

    // ---------------- decoder ----------------
    for (int t = 0; t < PRED; ++t) {
        const __nv_bfloat16* hr0h = g_h0h[par];
        const __nv_bfloat16* hr0l = g_h0l[par];
        __nv_bfloat16* hw0h = g_h0h[par ^ 1];
        __nv_bfloat16* hw0l = g_h0l[par ^ 1];
        const __nv_bfloat16* hr1h = g_h1h[par];
        const __nv_bfloat16* hr1l = g_h1l[par];
        __nv_bfloat16* hw1h = g_h1h[par ^ 1];
        __nv_bfloat16* hw1l = g_h1l[par ^ 1];

        // stage A: gates0 = h0 @ dWh0^T  (+ din * dWi0 in epilogue)
        ZERO_ACC();
        gemm_async(acc, sm, hr0h, hr0l, Hd, g_dWh0h + woff512, g_dWh0l + woff512, 512, bm0);
        epilogue<1>(acc, sm, c0r, dbi0, dbh0, hw0h, hw0l, bm0, hc0, tileN,
                    dWi0, y, tfm, d_out, t, (const float*)0, fcB);
        grid_bar(&phase);

        // stage B
        ZERO_ACC();
        gemm_async(acc, sm, hw0h, hw0l, Hd, g_dWi1h + woff512, g_dWi1l + woff512, 512, bm0);
        gemm_async(acc, sm, hr1h, hr1l, Hd, g_dWh1h + woff512, g_dWh1l + woff512, 512, bm0);
        epilogue<2>(acc, sm, c1r, dbi1, dbh1, hw1h, hw1l, bm0, hc0, tileN,
                    (const float*)0, (const float*)0, (const int*)0, (float*)0, t,
                    fcW, (const float*)0);
        grid_bar(&phase);
        par ^= 1;
    }

    // ---------------- final output (t = PRED-1) ----------------
    if (tileN == 0 && threadIdx.x < BM) {
        const int b = bm0 + threadIdx.x;
        float out = fcB[0];
#pragma unroll
        for (int j = 0; j < 16; ++j) out += g_fc_part[j][b];
        d_out[b * PRED + (PRED - 1)] = out;
    }
}

// ---------------- harness entry ----------------
extern "C" void kernel_launch(void* const* d_in, const int* in_sizes, int n_in,
                              void* d_out, int out_size) {
    const float* Xe  = (const float*)d_in[0];
    const float* Xd  = (const float*)d_in[1];
    const float* y   = (const float*)d_in[2];
    const int*   tfm = (const int*)d_in[3];
    const float* eWi0 = (const float*)d_in[4];
    const float* eWh0 = (const float*)d_in[5];
    const float* ebi0 = (const float*)d_in[6];
    const float* ebh0 = (const float*)d_in[7];
    const float* eWi1 = (const float*)d_in[8];
    const float* eWh1 = (const float*)d_in[9];
    const float* ebi1 = (const float*)d_in[10];
    const float* ebh1 = (const float*)d_in[11];
    const float* dWi0 = (const float*)d_in[12];
    const float* dWh0 = (const float*)d_in[13];
    const float* dbi0 = (const float*)d_in[14];
    const float* dbh0 = (const float*)d_in[15];
    const float* dWi1 = (const float*)d_in[16];
    const float* dWh1 = (const float*)d_in[17];
    const float* dbi1 = (const float*)d_in[18];
    const float* dbh1 = (const float*)d_in[19];
    const float* fcW  = (const float*)d_in[20];
    const float* fcB  = (const float*)d_in[21];
    float* out = (float*)d_out;

    cudaFuncSetAttribute(seq2seq_kernel,
                         cudaFuncAttributeMaxDynamicSharedMemorySize, SMEM_BYTES);

    init_kernel<<<1024, NTHR>>>(Xd, Xe, eWi0, eWh0, eWi1, eWh1, dWh0, dWi1, dWh1);
    seq2seq_kernel<<<GRIDSZ, NTHR, SMEM_BYTES>>>(y, tfm,
                                                 ebi0, ebh0, ebi1, ebh1,
                                                 dWi0, dbi0, dbh0, dbi1, dbh1,
                                                 fcW, fcB, out);
}